// round 1
// baseline (speedup 1.0000x reference)
#include <cuda_runtime.h>
#include <math.h>

#define FULL 0xffffffffu

// Scratch token buffer: (B=16, T=128, slots=67, EMBED=32) fp32 = 17.56 MB
__device__ float g_tokens[16 * 128 * 67 * 32];

__device__ __forceinline__ float warp_sum(float v) {
    v += __shfl_xor_sync(FULL, v, 16);
    v += __shfl_xor_sync(FULL, v, 8);
    v += __shfl_xor_sync(FULL, v, 4);
    v += __shfl_xor_sync(FULL, v, 2);
    v += __shfl_xor_sync(FULL, v, 1);
    return v;
}
__device__ __forceinline__ float warp_max(float v) {
    v = fmaxf(v, __shfl_xor_sync(FULL, v, 16));
    v = fmaxf(v, __shfl_xor_sync(FULL, v, 8));
    v = fmaxf(v, __shfl_xor_sync(FULL, v, 4));
    v = fmaxf(v, __shfl_xor_sync(FULL, v, 2));
    v = fmaxf(v, __shfl_xor_sync(FULL, v, 1));
    return v;
}
__device__ __forceinline__ float grp8_sum(float v) {
    v += __shfl_xor_sync(FULL, v, 1);
    v += __shfl_xor_sync(FULL, v, 2);
    v += __shfl_xor_sync(FULL, v, 4);
    return v;
}

// ---------------------------------------------------------------------------
// Kernel 0: tokenize + input rmsnorm.
// grid = B*T (2048), block = 256. Warp per slot (looped).
// ---------------------------------------------------------------------------
__global__ void embed_kernel(const float* __restrict__ obs,
                             const float* __restrict__ Wval,
                             const float* __restrict__ bval,
                             const float* __restrict__ innorm,
                             const float* __restrict__ dimemb,
                             const float* __restrict__ cls) {
    int bt = blockIdx.x;
    int tid = threadIdx.x;
    int wid = tid >> 5, lane = tid & 31;
    for (int s = wid; s < 67; s += 8) {
        float val;
        if (s < 64)
            val = fmaf(obs[bt * 64 + s], Wval[lane], bval[lane]) + dimemb[s * 32 + lane];
        else
            val = cls[(s - 64) * 32 + lane];
        float ms = warp_sum(val * val) * (1.f / 32.f);
        g_tokens[(bt * 67 + s) * 32 + lane] = val * rsqrtf(ms + 1e-6f) * innorm[lane];
    }
}

// ---------------------------------------------------------------------------
// Fused attention block: rmsnorm -> qkv proj -> qk-norm (-> rope) -> attn
// -> Wo + rmsnorm residual -> FFN (silu-gate) + rmsnorm residual.
// One CTA per sequence, 8 warps, warp-per-token.
// ---------------------------------------------------------------------------
template <int S, bool TEMPORAL>
__global__ void __launch_bounds__(256, 2)
attn_block(const float* __restrict__ Wq, const float* __restrict__ Wk,
           const float* __restrict__ Wv, const float* __restrict__ Wo,
           const float* __restrict__ Wg, const float* __restrict__ Wu,
           const float* __restrict__ Wout, const float* __restrict__ norm4,
           const float* __restrict__ qkn) {
    constexpr int SPAD = ((S + 31) / 32) * 32;   // 96 or 128
    constexpr int KPER = SPAD / 32;              // 3 or 4
    constexpr int NW = 8;
    constexpr int MAXIT = (S + NW - 1) / NW;     // 9 or 16
    constexpr int RP = 33;                       // padded row stride
    constexpr int PROW = SPAD + 1;               // padded prob-row stride

    extern __shared__ float sm[];
    float* sx    = sm;                    // SPAD*RP
    float* sk    = sx + SPAD * RP;        // SPAD*RP
    float* sv    = sk + SPAD * RP;        // SPAD*RP
    float* swq   = sv + SPAD * RP;        // 32*RP
    float* swk   = swq + 32 * RP;
    float* swv   = swk + 32 * RP;
    float* swo   = swv + 32 * RP;
    float* swg   = swo + 32 * RP;         // 64*RP
    float* swu   = swg + 64 * RP;         // 64*RP
    float* swout = swu + 64 * RP;         // 32*65
    float* snorm = swout + 32 * 65;       // 128
    float* sqkn  = snorm + 128;           // 16
    float* pbuf  = sqkn + 16;             // NW*4*PROW

    int tid = threadIdx.x;

    long base;
    int tstride;
    if (TEMPORAL) {
        int b = blockIdx.x / 67, s = blockIdx.x % 67;
        base = (long)b * (128 * 67 * 32) + (long)s * 32;
        tstride = 67 * 32;
    } else {
        base = (long)blockIdx.x * (67 * 32);
        tstride = 32;
    }
    float* gx = g_tokens + base;

    // ---- stage sequence + weights into smem ----
    for (int i = tid; i < S * 32; i += 256) {
        int t = i >> 5, w = i & 31;
        sx[t * RP + w] = gx[t * tstride + w];
    }
    for (int i = tid; i < (SPAD - S) * RP; i += 256) {
        sk[S * RP + i] = 0.f;
        sv[S * RP + i] = 0.f;
    }
    for (int i = tid; i < 1024; i += 256) {
        int d = i >> 5, w = i & 31;
        swq[d * RP + w] = Wq[i];
        swk[d * RP + w] = Wk[i];
        swv[d * RP + w] = Wv[i];
        swo[d * RP + w] = Wo[i];
    }
    for (int i = tid; i < 2048; i += 256) {
        int f = i >> 5, w = i & 31;
        swg[f * RP + w] = Wg[i];
        swu[f * RP + w] = Wu[i];
    }
    for (int i = tid; i < 2048; i += 256) {
        int d = i >> 6, f = i & 63;
        swout[d * 65 + f] = Wout[i];
    }
    if (tid < 128) snorm[tid] = norm4[tid];
    if (tid < 16) sqkn[tid] = qkn[tid];
    __syncthreads();

    int wid = tid >> 5, lane = tid & 31;
    int hd = lane & 7, head = lane >> 3;

    float rth = 0.f;
    if (TEMPORAL) rth = __powf(10000.f, -(float)(hd & 3) * 0.25f);

    // ---- phase B: per-token rmsnorm + qkv proj + qk-norm (+rope) ----
    float qsave[MAXIT];
#pragma unroll
    for (int it = 0; it < MAXIT; ++it) {
        int tok = wid + it * NW;
        qsave[it] = 0.f;
        if (tok < S) {
            float x = sx[tok * RP + lane];
            float ms = warp_sum(x * x) * (1.f / 32.f);
            float h = x * rsqrtf(ms + 1e-6f) * snorm[lane];
            float q = 0.f, k = 0.f, v = 0.f;
#pragma unroll
            for (int w = 0; w < 32; w++) {
                float hw = __shfl_sync(FULL, h, w);
                q = fmaf(hw, swq[lane * RP + w], q);
                k = fmaf(hw, swk[lane * RP + w], k);
                v = fmaf(hw, swv[lane * RP + w], v);
            }
            float qs = grp8_sum(q * q) * 0.125f;
            q = q * rsqrtf(qs + 1e-6f) * sqkn[hd];
            float ks = grp8_sum(k * k) * 0.125f;
            k = k * rsqrtf(ks + 1e-6f) * sqkn[8 + hd];
            if (TEMPORAL) {
                float fr = (float)tok * rth;
                float sn, cv;
                __sincosf(fr, &sn, &cv);
                float qp = __shfl_xor_sync(FULL, q, 4);
                float kp = __shfl_xor_sync(FULL, k, 4);
                q = (hd < 4) ? (q * cv - qp * sn) : fmaf(qp, sn, q * cv);
                k = (hd < 4) ? (k * cv - kp * sn) : fmaf(kp, sn, k * cv);
            }
            qsave[it] = q * 0.35355339059327373f;  // fold 1/sqrt(HD)
            sk[tok * RP + lane] = k;
            sv[tok * RP + lane] = v;
        }
    }
    __syncthreads();

    // ---- phase C: attention + Wo residual + FFN residual, per token ----
    float* pw = pbuf + wid * 4 * PROW;
#pragma unroll
    for (int it = 0; it < MAXIT; ++it) {
        int tok = wid + it * NW;
        if (tok >= S) break;
        float qreg = qsave[it];

        // scores: lane = key-token (strided), 4 heads per lane
        float sc[KPER][4];
#pragma unroll
        for (int r = 0; r < KPER; r++)
#pragma unroll
            for (int h2 = 0; h2 < 4; h2++) sc[r][h2] = 0.f;
#pragma unroll
        for (int c = 0; c < 32; c++) {
            float qc = __shfl_sync(FULL, qreg, c);
#pragma unroll
            for (int r = 0; r < KPER; r++)
                sc[r][c >> 3] = fmaf(qc, sk[(lane + 32 * r) * RP + c], sc[r][c >> 3]);
        }
#pragma unroll
        for (int r = 0; r < KPER; r++)
            if (lane + 32 * r >= S) {
                sc[r][0] = sc[r][1] = sc[r][2] = sc[r][3] = -1e30f;
            }

        // softmax (per head, across warp)
        float m[4], linv[4];
#pragma unroll
        for (int h2 = 0; h2 < 4; h2++) {
            float mm = sc[0][h2];
#pragma unroll
            for (int r = 1; r < KPER; r++) mm = fmaxf(mm, sc[r][h2]);
            m[h2] = warp_max(mm);
        }
#pragma unroll
        for (int h2 = 0; h2 < 4; h2++) {
            float ls = 0.f;
#pragma unroll
            for (int r = 0; r < KPER; r++) {
                float p = __expf(sc[r][h2] - m[h2]);
                sc[r][h2] = p;
                ls += p;
            }
            linv[h2] = __fdividef(1.f, warp_sum(ls));
        }
        __syncwarp();
#pragma unroll
        for (int r = 0; r < KPER; r++)
#pragma unroll
            for (int h2 = 0; h2 < 4; h2++)
                pw[h2 * PROW + lane + 32 * r] = sc[r][h2] * linv[h2];
        __syncwarp();

        // PV: lane = output dim
        float o = 0.f;
        const float* prow = pw + head * PROW;
#pragma unroll 8
        for (int j = 0; j < SPAD; j++) o = fmaf(prow[j], sv[j * RP + lane], o);

        // Wo projection + rmsnorm residual
        float ow = 0.f;
#pragma unroll
        for (int w = 0; w < 32; w++) {
            float ov = __shfl_sync(FULL, o, w);
            ow = fmaf(ov, swo[lane * RP + w], ow);
        }
        float r1 = ow * rsqrtf(warp_sum(ow * ow) * (1.f / 32.f) + 1e-6f) * snorm[32 + lane];
        float xn = sx[tok * RP + lane] + r1;

        // FFN
        float h2v = xn * rsqrtf(warp_sum(xn * xn) * (1.f / 32.f) + 1e-6f) * snorm[64 + lane];
        float g0 = 0.f, g1 = 0.f, u0 = 0.f, u1 = 0.f;
#pragma unroll
        for (int w = 0; w < 32; w++) {
            float hw = __shfl_sync(FULL, h2v, w);
            g0 = fmaf(hw, swg[lane * RP + w], g0);
            g1 = fmaf(hw, swg[(lane + 32) * RP + w], g1);
            u0 = fmaf(hw, swu[lane * RP + w], u0);
            u1 = fmaf(hw, swu[(lane + 32) * RP + w], u1);
        }
        float f0 = g0 * __fdividef(1.f, 1.f + __expf(-g0)) * u0;
        float f1 = g1 * __fdividef(1.f, 1.f + __expf(-g1)) * u1;
        float outv = 0.f;
#pragma unroll
        for (int f = 0; f < 32; f++) {
            float fv = __shfl_sync(FULL, f0, f);
            outv = fmaf(fv, swout[lane * 65 + f], outv);
        }
#pragma unroll
        for (int f = 0; f < 32; f++) {
            float fv = __shfl_sync(FULL, f1, f);
            outv = fmaf(fv, swout[lane * 65 + 32 + f], outv);
        }
        float r3 = outv * rsqrtf(warp_sum(outv * outv) * (1.f / 32.f) + 1e-6f) * snorm[96 + lane];
        gx[tok * tstride + lane] = xn + r3;
        __syncwarp();
    }
}

// ---------------------------------------------------------------------------
// Final: rmsnorm + extract 3 CLS tokens of last timestep. grid=48, block=32.
// ---------------------------------------------------------------------------
__global__ void final_kernel(const float* __restrict__ fnorm, float* __restrict__ out) {
    int b = blockIdx.x / 3, k = blockIdx.x % 3, lane = threadIdx.x;
    float x = g_tokens[(((long)b * 128 + 127) * 67 + 64 + k) * 32 + lane];
    float ms = warp_sum(x * x) * (1.f / 32.f);
    out[(k * 16 + b) * 32 + lane] = x * rsqrtf(ms + 1e-6f) * fnorm[lane];
}

// ---------------------------------------------------------------------------
// Launch
// ---------------------------------------------------------------------------
extern "C" void kernel_launch(void* const* d_in, const int* in_sizes, int n_in,
                              void* d_out, int out_size) {
    const float* obs    = (const float*)d_in[0];
    const float* Wval   = (const float*)d_in[1];
    const float* bval   = (const float*)d_in[2];
    const float* innorm = (const float*)d_in[3];
    const float* dimemb = (const float*)d_in[4];
    const float* cls    = (const float*)d_in[5];
    const float* fnorm  = (const float*)d_in[6];
    const float* sWq   = (const float*)d_in[7];
    const float* sWk   = (const float*)d_in[8];
    const float* sWv   = (const float*)d_in[9];
    const float* sWo   = (const float*)d_in[10];
    const float* sWg   = (const float*)d_in[11];
    const float* sWu   = (const float*)d_in[12];
    const float* sWout = (const float*)d_in[13];
    const float* sN4   = (const float*)d_in[14];
    const float* sQKN  = (const float*)d_in[15];
    const float* tWq   = (const float*)d_in[16];
    const float* tWk   = (const float*)d_in[17];
    const float* tWv   = (const float*)d_in[18];
    const float* tWo   = (const float*)d_in[19];
    const float* tWg   = (const float*)d_in[20];
    const float* tWu   = (const float*)d_in[21];
    const float* tWout = (const float*)d_in[22];
    const float* tN4   = (const float*)d_in[23];
    const float* tQKN  = (const float*)d_in[24];

    // dynamic smem sizes (floats): 3*SPAD*33 + 4*32*33 + 2*64*33 + 32*65 + 128 + 16 + 32*(SPAD+1)
    const int SZ67  = (3 * 96 * 33 + 4 * 32 * 33 + 2 * 64 * 33 + 32 * 65 + 128 + 16 + 32 * 97) * 4;
    const int SZ128 = (3 * 128 * 33 + 4 * 32 * 33 + 2 * 64 * 33 + 32 * 65 + 128 + 16 + 32 * 129) * 4;

    cudaFuncSetAttribute(attn_block<67, false>, cudaFuncAttributeMaxDynamicSharedMemorySize, SZ67);
    cudaFuncSetAttribute(attn_block<128, true>, cudaFuncAttributeMaxDynamicSharedMemorySize, SZ128);

    embed_kernel<<<2048, 256>>>(obs, Wval, bval, innorm, dimemb, cls);

    for (int layer = 0; layer < 3; layer++) {
        attn_block<67, false><<<2048, 256, SZ67>>>(
            sWq + layer * 1024, sWk + layer * 1024, sWv + layer * 1024, sWo + layer * 1024,
            sWg + layer * 2048, sWu + layer * 2048, sWout + layer * 2048,
            sN4 + layer * 128, sQKN + layer * 16);
        if (layer < 2) {
            attn_block<128, true><<<1072, 256, SZ128>>>(
                tWq + layer * 1024, tWk + layer * 1024, tWv + layer * 1024, tWo + layer * 1024,
                tWg + layer * 2048, tWu + layer * 2048, tWout + layer * 2048,
                tN4 + layer * 128, tQKN + layer * 16);
        }
    }

    final_kernel<<<48, 32>>>(fnorm, (float*)d_out);
}

// round 2
// speedup vs baseline: 1.5356x; 1.5356x over previous
#include <cuda_runtime.h>
#include <math.h>

#define FULL 0xffffffffu

// Scratch token buffer: (B=16, T=128, slots=67, EMBED=32) fp32 = 17.56 MB
__device__ float g_tokens[16 * 128 * 67 * 32];

__device__ __forceinline__ float warp_sum(float v) {
    v += __shfl_xor_sync(FULL, v, 16);
    v += __shfl_xor_sync(FULL, v, 8);
    v += __shfl_xor_sync(FULL, v, 4);
    v += __shfl_xor_sync(FULL, v, 2);
    v += __shfl_xor_sync(FULL, v, 1);
    return v;
}
__device__ __forceinline__ float grp8_sum(float v) {
    v += __shfl_xor_sync(FULL, v, 1);
    v += __shfl_xor_sync(FULL, v, 2);
    v += __shfl_xor_sync(FULL, v, 4);
    return v;
}
__device__ __forceinline__ float grp8_max(float v) {
    v = fmaxf(v, __shfl_xor_sync(FULL, v, 1));
    v = fmaxf(v, __shfl_xor_sync(FULL, v, 2));
    v = fmaxf(v, __shfl_xor_sync(FULL, v, 4));
    return v;
}

// ---------------------------------------------------------------------------
// Kernel 0: tokenize + input rmsnorm. grid = B*T (2048), block = 256.
// ---------------------------------------------------------------------------
__global__ void embed_kernel(const float* __restrict__ obs,
                             const float* __restrict__ Wval,
                             const float* __restrict__ bval,
                             const float* __restrict__ innorm,
                             const float* __restrict__ dimemb,
                             const float* __restrict__ cls) {
    int bt = blockIdx.x;
    int tid = threadIdx.x;
    int wid = tid >> 5, lane = tid & 31;
    for (int s = wid; s < 67; s += 8) {
        float val;
        if (s < 64)
            val = fmaf(obs[bt * 64 + s], Wval[lane], bval[lane]) + dimemb[s * 32 + lane];
        else
            val = cls[(s - 64) * 32 + lane];
        float ms = warp_sum(val * val) * (1.f / 32.f);
        g_tokens[(bt * 67 + s) * 32 + lane] = val * rsqrtf(ms + 1e-6f) * innorm[lane];
    }
}

// ---------------------------------------------------------------------------
// Fused attention block, Q query-tokens batched per warp iteration.
// Lane layouts:
//   projections / PV output / FFN: lane = embed dim (or f, f+32)
//   scores/probs: head = lane>>3, key = (lane&7) + 8*r  (r = register idx)
// Probabilities travel scores->PV via computed-source-lane shuffles: the
// value for (key j, head h) lives at lane h*8+(j&7), register j>>3. No smem
// transpose, no prob buffer.
// ---------------------------------------------------------------------------
template <int S, int Q, bool TEMPORAL>
__global__ void __launch_bounds__(256, 2)
attn_block(const float* __restrict__ Wq, const float* __restrict__ Wk,
           const float* __restrict__ Wv, const float* __restrict__ Wo,
           const float* __restrict__ Wg, const float* __restrict__ Wu,
           const float* __restrict__ Wout, const float* __restrict__ norm4,
           const float* __restrict__ qkn) {
    constexpr int SPAD = ((S + 31) / 32) * 32;   // 96 or 128
    constexpr int NR = SPAD / 8;                 // 12 or 16 prob regs / lane
    constexpr int RP = 33;
    constexpr int CH = (S + 7) / 8;              // tokens per warp

    extern __shared__ float sm[];
    float* sx    = sm;                    // SPAD*RP
    float* sk    = sx + SPAD * RP;
    float* sv    = sk + SPAD * RP;
    float* sq    = sv + SPAD * RP;
    float* swq   = sq + SPAD * RP;        // 32*RP each
    float* swk   = swq + 32 * RP;
    float* swv   = swk + 32 * RP;
    float* swo   = swv + 32 * RP;
    float* swg   = swo + 32 * RP;         // 64*RP
    float* swu   = swg + 64 * RP;         // 64*RP
    float* swout = swu + 64 * RP;         // 32*65
    float* snorm = swout + 32 * 65;       // 128
    float* sqkn  = snorm + 128;           // 16

    int tid = threadIdx.x;

    long base_g;
    int tstride;
    if (TEMPORAL) {
        int b = blockIdx.x / 67, s = blockIdx.x % 67;
        base_g = (long)b * (128 * 67 * 32) + (long)s * 32;
        tstride = 67 * 32;
    } else {
        base_g = (long)blockIdx.x * (67 * 32);
        tstride = 32;
    }
    float* gx = g_tokens + base_g;

    // ---- stage sequence + weights ----
    for (int i = tid; i < S * 32; i += 256) {
        int t = i >> 5, w = i & 31;
        sx[t * RP + w] = gx[t * tstride + w];
    }
    for (int i = tid; i < (SPAD - S) * RP; i += 256) {
        sk[S * RP + i] = 0.f;
        sv[S * RP + i] = 0.f;
    }
    for (int i = tid; i < 1024; i += 256) {
        int d = i >> 5, w = i & 31;
        swq[d * RP + w] = Wq[i];
        swk[d * RP + w] = Wk[i];
        swv[d * RP + w] = Wv[i];
        swo[d * RP + w] = Wo[i];
    }
    for (int i = tid; i < 2048; i += 256) {
        int f = i >> 5, w = i & 31;
        swg[f * RP + w] = Wg[i];
        swu[f * RP + w] = Wu[i];
    }
    for (int i = tid; i < 2048; i += 256) {
        int d = i >> 6, f = i & 63;
        swout[d * 65 + f] = Wout[i];
    }
    if (tid < 128) snorm[tid] = norm4[tid];
    if (tid < 16) sqkn[tid] = qkn[tid];
    __syncthreads();

    int wid = tid >> 5, lane = tid & 31;
    int hd = lane & 7;
    int tok0 = wid * CH;
    int tok_end = min(tok0 + CH, S);

    float rth = 0.f;
    if (TEMPORAL) rth = __powf(10000.f, -(float)(hd & 3) * 0.25f);

    // ================= Phase B: norm + QKV + qk-norm + rope =================
#pragma unroll 1
    for (int gb = tok0; gb < tok_end; gb += Q) {
        float h[Q], qa[Q], ka[Q], va[Q];
#pragma unroll
        for (int q = 0; q < Q; q++) {
            int t = gb + q;
            if (t >= tok_end) t = tok_end - 1;
            float x = sx[t * RP + lane];
            float ms = warp_sum(x * x) * (1.f / 32.f);
            h[q] = x * rsqrtf(ms + 1e-6f) * snorm[lane];
            qa[q] = ka[q] = va[q] = 0.f;
        }
#pragma unroll
        for (int w = 0; w < 32; w++) {
            float wwq = swq[lane * RP + w];
            float wwk = swk[lane * RP + w];
            float wwv = swv[lane * RP + w];
#pragma unroll
            for (int q = 0; q < Q; q++) {
                float hw = __shfl_sync(FULL, h[q], w);
                qa[q] = fmaf(hw, wwq, qa[q]);
                ka[q] = fmaf(hw, wwk, ka[q]);
                va[q] = fmaf(hw, wwv, va[q]);
            }
        }
#pragma unroll
        for (int q = 0; q < Q; q++) {
            float qs = grp8_sum(qa[q] * qa[q]) * 0.125f;
            float qv = qa[q] * rsqrtf(qs + 1e-6f) * sqkn[hd];
            float ks = grp8_sum(ka[q] * ka[q]) * 0.125f;
            float kv = ka[q] * rsqrtf(ks + 1e-6f) * sqkn[8 + hd];
            if (TEMPORAL) {
                float fr = (float)(gb + q) * rth;
                float sn, cv;
                __sincosf(fr, &sn, &cv);
                float qp = __shfl_xor_sync(FULL, qv, 4);
                float kp = __shfl_xor_sync(FULL, kv, 4);
                qv = (hd < 4) ? (qv * cv - qp * sn) : fmaf(qp, sn, qv * cv);
                kv = (hd < 4) ? (kv * cv - kp * sn) : fmaf(kp, sn, kv * cv);
            }
            if (gb + q < tok_end) {
                sq[(gb + q) * RP + lane] = qv * 0.35355339059327373f;  // 1/sqrt(HD)
                sk[(gb + q) * RP + lane] = kv;
                sv[(gb + q) * RP + lane] = va[q];
            }
        }
    }
    __syncthreads();

    // ================= Phase C: attention + Wo + FFN =================
    int hbase = lane & 24;   // head*8
    int k7 = lane & 7;

#pragma unroll 1
    for (int gb = tok0; gb < tok_end; gb += Q) {
        float qr[Q];
#pragma unroll
        for (int q = 0; q < Q; q++) {
            int t = gb + q;
            if (t >= tok_end) t = tok_end - 1;
            qr[q] = sq[t * RP + lane];
        }

        // ---- scores: lane holds keys (k7+8r) of head (lane>>3) ----
        float sc[Q][NR];
#pragma unroll
        for (int q = 0; q < Q; q++)
#pragma unroll
            for (int r = 0; r < NR; r++) sc[q][r] = 0.f;

#pragma unroll
        for (int c0 = 0; c0 < 8; c0++) {
            float qc[Q];
#pragma unroll
            for (int q = 0; q < Q; q++) qc[q] = __shfl_sync(FULL, qr[q], hbase + c0);
#pragma unroll
            for (int r = 0; r < NR; r++) {
                float kv = sk[(k7 + 8 * r) * RP + hbase + c0];
#pragma unroll
                for (int q = 0; q < Q; q++) sc[q][r] = fmaf(qc[q], kv, sc[q][r]);
            }
        }
#pragma unroll
        for (int r = 0; r < NR; r++)
            if (k7 + 8 * r >= S) {
#pragma unroll
                for (int q = 0; q < Q; q++) sc[q][r] = -1e30f;
            }

        // ---- softmax within each head's 8 lanes ----
#pragma unroll
        for (int q = 0; q < Q; q++) {
            float mm = sc[q][0];
#pragma unroll
            for (int r = 1; r < NR; r++) mm = fmaxf(mm, sc[q][r]);
            mm = grp8_max(mm);
            float ls = 0.f;
#pragma unroll
            for (int r = 0; r < NR; r++) {
                float p = __expf(sc[q][r] - mm);
                sc[q][r] = p;
                ls += p;
            }
            float linv = __fdividef(1.f, grp8_sum(ls));
#pragma unroll
            for (int r = 0; r < NR; r++) sc[q][r] *= linv;
        }

        // ---- PV: prob for (key j, head lane>>3) = shfl(sc[j>>3], hbase|(j&7)) ----
        float o[Q];
#pragma unroll
        for (int q = 0; q < Q; q++) o[q] = 0.f;
#pragma unroll
        for (int r = 0; r < NR; r++) {
#pragma unroll
            for (int j7 = 0; j7 < 8; j7++) {
                float vj = sv[(8 * r + j7) * RP + lane];
#pragma unroll
                for (int q = 0; q < Q; q++) {
                    float pj = __shfl_sync(FULL, sc[q][r], hbase + j7);
                    o[q] = fmaf(pj, vj, o[q]);
                }
            }
        }

        // ---- Wo + rmsnorm residual ----
        float ow[Q];
#pragma unroll
        for (int q = 0; q < Q; q++) ow[q] = 0.f;
#pragma unroll
        for (int w = 0; w < 32; w++) {
            float wo = swo[lane * RP + w];
#pragma unroll
            for (int q = 0; q < Q; q++)
                ow[q] = fmaf(__shfl_sync(FULL, o[q], w), wo, ow[q]);
        }
        float xn[Q], h2[Q];
#pragma unroll
        for (int q = 0; q < Q; q++) {
            float r1 = ow[q] * rsqrtf(warp_sum(ow[q] * ow[q]) * (1.f / 32.f) + 1e-6f) * snorm[32 + lane];
            int t = gb + q;
            if (t >= tok_end) t = tok_end - 1;
            xn[q] = sx[t * RP + lane] + r1;
            h2[q] = xn[q] * rsqrtf(warp_sum(xn[q] * xn[q]) * (1.f / 32.f) + 1e-6f) * snorm[64 + lane];
        }

        // ---- FFN ----
        float g0[Q], g1[Q], u0[Q], u1[Q];
#pragma unroll
        for (int q = 0; q < Q; q++) g0[q] = g1[q] = u0[q] = u1[q] = 0.f;
#pragma unroll
        for (int w = 0; w < 32; w++) {
            float wg0 = swg[lane * RP + w];
            float wg1 = swg[(lane + 32) * RP + w];
            float wu0 = swu[lane * RP + w];
            float wu1 = swu[(lane + 32) * RP + w];
#pragma unroll
            for (int q = 0; q < Q; q++) {
                float hw = __shfl_sync(FULL, h2[q], w);
                g0[q] = fmaf(hw, wg0, g0[q]);
                g1[q] = fmaf(hw, wg1, g1[q]);
                u0[q] = fmaf(hw, wu0, u0[q]);
                u1[q] = fmaf(hw, wu1, u1[q]);
            }
        }
        float f0[Q], f1[Q], outv[Q];
#pragma unroll
        for (int q = 0; q < Q; q++) {
            f0[q] = g0[q] * __fdividef(1.f, 1.f + __expf(-g0[q])) * u0[q];
            f1[q] = g1[q] * __fdividef(1.f, 1.f + __expf(-g1[q])) * u1[q];
            outv[q] = 0.f;
        }
#pragma unroll
        for (int f = 0; f < 32; f++) {
            float wa = swout[lane * 65 + f];
            float wb = swout[lane * 65 + 32 + f];
#pragma unroll
            for (int q = 0; q < Q; q++) {
                outv[q] = fmaf(__shfl_sync(FULL, f0[q], f), wa, outv[q]);
                outv[q] = fmaf(__shfl_sync(FULL, f1[q], f), wb, outv[q]);
            }
        }
#pragma unroll
        for (int q = 0; q < Q; q++) {
            float r3 = outv[q] * rsqrtf(warp_sum(outv[q] * outv[q]) * (1.f / 32.f) + 1e-6f) * snorm[96 + lane];
            if (gb + q < tok_end) gx[(gb + q) * tstride + lane] = xn[q] + r3;
        }
    }
}

// ---------------------------------------------------------------------------
// Final: rmsnorm + extract 3 CLS tokens of last timestep.
// ---------------------------------------------------------------------------
__global__ void final_kernel(const float* __restrict__ fnorm, float* __restrict__ out) {
    int b = blockIdx.x / 3, k = blockIdx.x % 3, lane = threadIdx.x;
    float x = g_tokens[(((long)b * 128 + 127) * 67 + 64 + k) * 32 + lane];
    float ms = warp_sum(x * x) * (1.f / 32.f);
    out[(k * 16 + b) * 32 + lane] = x * rsqrtf(ms + 1e-6f) * fnorm[lane];
}

// ---------------------------------------------------------------------------
// Launch
// ---------------------------------------------------------------------------
extern "C" void kernel_launch(void* const* d_in, const int* in_sizes, int n_in,
                              void* d_out, int out_size) {
    const float* obs    = (const float*)d_in[0];
    const float* Wval   = (const float*)d_in[1];
    const float* bval   = (const float*)d_in[2];
    const float* innorm = (const float*)d_in[3];
    const float* dimemb = (const float*)d_in[4];
    const float* cls    = (const float*)d_in[5];
    const float* fnorm  = (const float*)d_in[6];
    const float* sWq   = (const float*)d_in[7];
    const float* sWk   = (const float*)d_in[8];
    const float* sWv   = (const float*)d_in[9];
    const float* sWo   = (const float*)d_in[10];
    const float* sWg   = (const float*)d_in[11];
    const float* sWu   = (const float*)d_in[12];
    const float* sWout = (const float*)d_in[13];
    const float* sN4   = (const float*)d_in[14];
    const float* sQKN  = (const float*)d_in[15];
    const float* tWq   = (const float*)d_in[16];
    const float* tWk   = (const float*)d_in[17];
    const float* tWv   = (const float*)d_in[18];
    const float* tWo   = (const float*)d_in[19];
    const float* tWg   = (const float*)d_in[20];
    const float* tWu   = (const float*)d_in[21];
    const float* tWout = (const float*)d_in[22];
    const float* tN4   = (const float*)d_in[23];
    const float* tQKN  = (const float*)d_in[24];

    // smem floats: 4*SPAD*33 + 4*32*33 + 2*64*33 + 32*65 + 128 + 16
    const int SZ67  = (4 * 96 * 33 + 4 * 32 * 33 + 2 * 64 * 33 + 32 * 65 + 128 + 16) * 4;
    const int SZ128 = (4 * 128 * 33 + 4 * 32 * 33 + 2 * 64 * 33 + 32 * 65 + 128 + 16) * 4;

    cudaFuncSetAttribute(attn_block<67, 4, false>, cudaFuncAttributeMaxDynamicSharedMemorySize, SZ67);
    cudaFuncSetAttribute(attn_block<128, 4, true>, cudaFuncAttributeMaxDynamicSharedMemorySize, SZ128);

    embed_kernel<<<2048, 256>>>(obs, Wval, bval, innorm, dimemb, cls);

    for (int layer = 0; layer < 3; layer++) {
        attn_block<67, 4, false><<<2048, 256, SZ67>>>(
            sWq + layer * 1024, sWk + layer * 1024, sWv + layer * 1024, sWo + layer * 1024,
            sWg + layer * 2048, sWu + layer * 2048, sWout + layer * 2048,
            sN4 + layer * 128, sQKN + layer * 16);
        if (layer < 2) {
            attn_block<128, 4, true><<<1072, 256, SZ128>>>(
                tWq + layer * 1024, tWk + layer * 1024, tWv + layer * 1024, tWo + layer * 1024,
                tWg + layer * 2048, tWu + layer * 2048, tWout + layer * 2048,
                tN4 + layer * 128, tQKN + layer * 16);
        }
    }

    final_kernel<<<48, 32>>>(fnorm, (float*)d_out);
}

// round 3
// speedup vs baseline: 2.5173x; 1.6393x over previous
#include <cuda_runtime.h>
#include <math.h>

#define FULL 0xffffffffu

// Scratch token buffer: (B=16, T=128, slots=67, EMBED=32) fp32
__device__ float g_tokens[16 * 128 * 67 * 32];

__device__ __forceinline__ float warp_sum(float v) {
    v += __shfl_xor_sync(FULL, v, 16);
    v += __shfl_xor_sync(FULL, v, 8);
    v += __shfl_xor_sync(FULL, v, 4);
    v += __shfl_xor_sync(FULL, v, 2);
    v += __shfl_xor_sync(FULL, v, 1);
    return v;
}

// ---------------------------------------------------------------------------
// Kernel 0: tokenize + input rmsnorm. grid = B*T (2048), block = 256.
// ---------------------------------------------------------------------------
__global__ void embed_kernel(const float* __restrict__ obs,
                             const float* __restrict__ Wval,
                             const float* __restrict__ bval,
                             const float* __restrict__ innorm,
                             const float* __restrict__ dimemb,
                             const float* __restrict__ cls) {
    int bt = blockIdx.x;
    int tid = threadIdx.x;
    int wid = tid >> 5, lane = tid & 31;
    for (int s = wid; s < 67; s += 8) {
        float val;
        if (s < 64)
            val = fmaf(obs[bt * 64 + s], Wval[lane], bval[lane]) + dimemb[s * 32 + lane];
        else
            val = cls[(s - 64) * 32 + lane];
        float ms = warp_sum(val * val) * (1.f / 32.f);
        g_tokens[(bt * 67 + s) * 32 + lane] = val * rsqrtf(ms + 1e-6f) * innorm[lane];
    }
}

// ---------------------------------------------------------------------------
// Token-per-lane fused attention block.
// Each lane owns one whole token (all 32 embed dims in registers).
// Weights broadcast from smem via float4 LDS. K/V staged in smem rows of
// 36 floats (pad => conflict-free STS.128 + aligned LDS.128 broadcasts).
// Softmax without max-subtraction (|s|<=2.83 since q,k rms-normalized).
// ---------------------------------------------------------------------------
template <int S, int NSEQ, bool TEMPORAL>
__global__ void __launch_bounds__(32 * ((S * NSEQ + 31) / 32), 2)
attn_tpl(const float* __restrict__ Wq, const float* __restrict__ Wk,
         const float* __restrict__ Wv, const float* __restrict__ Wo,
         const float* __restrict__ Wg, const float* __restrict__ Wu,
         const float* __restrict__ Wout, const float* __restrict__ norm4,
         const float* __restrict__ qkn, int nseq_total) {
    constexpr int BLK = 32 * ((S * NSEQ + 31) / 32);
    constexpr int KVROW = 36;                 // padded row (floats)
    constexpr int KVSZ = NSEQ * 2 * S * KVROW;

    extern __shared__ float sm[];
    float* skv   = sm;                // KVSZ
    float* swq   = skv + KVSZ;        // 1024
    float* swk   = swq + 1024;
    float* swv   = swk + 1024;
    float* swo   = swv + 1024;
    float* swg   = swo + 1024;        // 2048
    float* swu   = swg + 2048;        // 2048
    float* swout = swu + 2048;        // 2048
    float* snorm = swout + 2048;      // 128
    float* sqkn  = snorm + 128;       // 16

    const int tid = threadIdx.x;

    // ---- stage weights (linear float4 copies) ----
    for (int i = tid; i < 256; i += BLK) {
        ((float4*)swq)[i] = ((const float4*)Wq)[i];
        ((float4*)swk)[i] = ((const float4*)Wk)[i];
        ((float4*)swv)[i] = ((const float4*)Wv)[i];
        ((float4*)swo)[i] = ((const float4*)Wo)[i];
    }
    for (int i = tid; i < 512; i += BLK) {
        ((float4*)swg)[i] = ((const float4*)Wg)[i];
        ((float4*)swu)[i] = ((const float4*)Wu)[i];
        ((float4*)swout)[i] = ((const float4*)Wout)[i];
    }
    if (tid < 32) ((float4*)snorm)[tid] = ((const float4*)norm4)[tid];
    if (tid < 4) ((float4*)sqkn)[tid] = ((const float4*)qkn)[tid];
    __syncthreads();

    // ---- per-lane token assignment ----
    int gseq0 = blockIdx.x * NSEQ;
    int nvalid = (min(gseq0 + NSEQ, nseq_total) - gseq0) * S;
    bool valid = tid < nvalid;
    int tcl = valid ? tid : (nvalid - 1);
    int seq = tcl / S;
    int tok = tcl - seq * S;

    float* kb = skv + seq * (2 * S * KVROW);
    float* vb = kb + S * KVROW;

    float* gx;
    if (TEMPORAL) {
        int gs = gseq0 + seq;
        int b = gs / 67, sl = gs - b * 67;
        gx = g_tokens + ((long)b * 128 * 67 + (long)tok * 67 + sl) * 32;
    } else {
        gx = g_tokens + ((long)(gseq0 + seq) * 67 + tok) * 32;
    }

    // qk-norm weights in registers (uniformish); fold 1/sqrt(8) into Q's.
    float qknQ[8], qknK[8];
#pragma unroll
    for (int e = 0; e < 8; e++) {
        qknQ[e] = sqkn[e] * 0.35355339059327373f;
        qknK[e] = sqkn[8 + e];
    }

    float cs4[4], sn4[4];
    if (TEMPORAL) {
        const float th[4] = {1.f, 0.1f, 0.01f, 0.001f};
#pragma unroll
        for (int j = 0; j < 4; j++) __sincosf((float)tok * th[j], &sn4[j], &cs4[j]);
    }

    // ================= Phase B: h = rmsnorm(x); K,V,Q projections ==========
    float h[32];
    {
        float xx[32];
#pragma unroll
        for (int c = 0; c < 8; c++) {
            float4 t = *(const float4*)(gx + 4 * c);
            xx[4 * c] = t.x; xx[4 * c + 1] = t.y; xx[4 * c + 2] = t.z; xx[4 * c + 3] = t.w;
        }
        float s0 = 0, s1 = 0, s2 = 0, s3 = 0;
#pragma unroll
        for (int c = 0; c < 8; c++) {
            s0 = fmaf(xx[4 * c], xx[4 * c], s0);
            s1 = fmaf(xx[4 * c + 1], xx[4 * c + 1], s1);
            s2 = fmaf(xx[4 * c + 2], xx[4 * c + 2], s2);
            s3 = fmaf(xx[4 * c + 3], xx[4 * c + 3], s3);
        }
        float rs = rsqrtf(((s0 + s1) + (s2 + s3)) * 0.03125f + 1e-6f);
#pragma unroll
        for (int c = 0; c < 8; c++) {
            float4 nw = *(const float4*)(snorm + 4 * c);
            h[4 * c] = xx[4 * c] * rs * nw.x;
            h[4 * c + 1] = xx[4 * c + 1] * rs * nw.y;
            h[4 * c + 2] = xx[4 * c + 2] * rs * nw.z;
            h[4 * c + 3] = xx[4 * c + 3] * rs * nw.w;
        }
    }

    // ---- K: per-head (rolled), qk-norm + rope, store to smem ----
#pragma unroll 1
    for (int hh = 0; hh < 4; hh++) {
        float a[8];
#pragma unroll
        for (int e = 0; e < 8; e++) {
            const float4* w4 = (const float4*)(swk + (hh * 8 + e) * 32);
            float b0 = 0, b1 = 0, b2 = 0, b3 = 0;
#pragma unroll
            for (int c = 0; c < 8; c++) {
                float4 w = w4[c];
                b0 = fmaf(h[4 * c], w.x, b0);
                b1 = fmaf(h[4 * c + 1], w.y, b1);
                b2 = fmaf(h[4 * c + 2], w.z, b2);
                b3 = fmaf(h[4 * c + 3], w.w, b3);
            }
            a[e] = (b0 + b1) + (b2 + b3);
        }
        float ms = 0;
#pragma unroll
        for (int e = 0; e < 8; e++) ms = fmaf(a[e], a[e], ms);
        float sc = rsqrtf(ms * 0.125f + 1e-6f);
#pragma unroll
        for (int e = 0; e < 8; e++) a[e] *= sc * qknK[e];
        if (TEMPORAL) {
#pragma unroll
            for (int e = 0; e < 4; e++) {
                float aa = a[e], bb = a[e + 4];
                a[e] = aa * cs4[e] - bb * sn4[e];
                a[e + 4] = fmaf(aa, sn4[e], bb * cs4[e]);
            }
        }
        if (valid) {
            float* dst = kb + tok * KVROW + hh * 8;
            *(float4*)dst = make_float4(a[0], a[1], a[2], a[3]);
            *(float4*)(dst + 4) = make_float4(a[4], a[5], a[6], a[7]);
        }
    }

    // ---- V: per-head (rolled), store ----
#pragma unroll 1
    for (int hh = 0; hh < 4; hh++) {
        float a[8];
#pragma unroll
        for (int e = 0; e < 8; e++) {
            const float4* w4 = (const float4*)(swv + (hh * 8 + e) * 32);
            float b0 = 0, b1 = 0, b2 = 0, b3 = 0;
#pragma unroll
            for (int c = 0; c < 8; c++) {
                float4 w = w4[c];
                b0 = fmaf(h[4 * c], w.x, b0);
                b1 = fmaf(h[4 * c + 1], w.y, b1);
                b2 = fmaf(h[4 * c + 2], w.z, b2);
                b3 = fmaf(h[4 * c + 3], w.w, b3);
            }
            a[e] = (b0 + b1) + (b2 + b3);
        }
        if (valid) {
            float* dst = vb + tok * KVROW + hh * 8;
            *(float4*)dst = make_float4(a[0], a[1], a[2], a[3]);
            *(float4*)(dst + 4) = make_float4(a[4], a[5], a[6], a[7]);
        }
    }

    // ---- Q: fully unrolled (needs const-indexed registers) ----
    float q[32];
#pragma unroll
    for (int hh = 0; hh < 4; hh++) {
        float a[8];
#pragma unroll
        for (int e = 0; e < 8; e++) {
            const float4* w4 = (const float4*)(swq + (hh * 8 + e) * 32);
            float b0 = 0, b1 = 0, b2 = 0, b3 = 0;
#pragma unroll
            for (int c = 0; c < 8; c++) {
                float4 w = w4[c];
                b0 = fmaf(h[4 * c], w.x, b0);
                b1 = fmaf(h[4 * c + 1], w.y, b1);
                b2 = fmaf(h[4 * c + 2], w.z, b2);
                b3 = fmaf(h[4 * c + 3], w.w, b3);
            }
            a[e] = (b0 + b1) + (b2 + b3);
        }
        float ms = 0;
#pragma unroll
        for (int e = 0; e < 8; e++) ms = fmaf(a[e], a[e], ms);
        float sc = rsqrtf(ms * 0.125f + 1e-6f);
#pragma unroll
        for (int e = 0; e < 8; e++) a[e] *= sc * qknQ[e];
        if (TEMPORAL) {
#pragma unroll
            for (int e = 0; e < 4; e++) {
                float aa = a[e], bb = a[e + 4];
                a[e] = aa * cs4[e] - bb * sn4[e];
                a[e + 4] = fmaf(aa, sn4[e], bb * cs4[e]);
            }
        }
#pragma unroll
        for (int e = 0; e < 8; e++) q[hh * 8 + e] = a[e];
    }
    __syncthreads();

    // ================= Phase C: streaming attention ========================
    float o[32];
#pragma unroll
    for (int d = 0; d < 32; d++) o[d] = 0.f;
    float l[4] = {0.f, 0.f, 0.f, 0.f};

#pragma unroll 2
    for (int j = 0; j < S; j++) {
        const float4* kr = (const float4*)(kb + j * KVROW);
        float s[4] = {0.f, 0.f, 0.f, 0.f};
#pragma unroll
        for (int c = 0; c < 8; c++) {
            float4 kc = kr[c];
            s[c >> 1] += fmaf(q[4 * c], kc.x,
                        fmaf(q[4 * c + 1], kc.y,
                        fmaf(q[4 * c + 2], kc.z, q[4 * c + 3] * kc.w)));
        }
        float p[4];
#pragma unroll
        for (int hh = 0; hh < 4; hh++) {
            p[hh] = __expf(s[hh]);
            l[hh] += p[hh];
        }
        const float4* vr = (const float4*)(vb + j * KVROW);
#pragma unroll
        for (int c = 0; c < 8; c++) {
            float4 vc = vr[c];
            float pp = p[c >> 1];
            o[4 * c] = fmaf(pp, vc.x, o[4 * c]);
            o[4 * c + 1] = fmaf(pp, vc.y, o[4 * c + 1]);
            o[4 * c + 2] = fmaf(pp, vc.z, o[4 * c + 2]);
            o[4 * c + 3] = fmaf(pp, vc.w, o[4 * c + 3]);
        }
    }
    {
        float li[4];
#pragma unroll
        for (int hh = 0; hh < 4; hh++) li[hh] = __fdividef(1.f, l[hh]);
#pragma unroll
        for (int d = 0; d < 32; d++) o[d] *= li[d >> 3];
    }

    // kv consumed by everyone -> reuse as per-lane scratch
    __syncthreads();
    float* scr = skv + tid * 33;

    // ---- Wo (rolled by 8-row group, sumsq on the fly, rows to scratch) ----
    float sumsq = 0.f;
#pragma unroll 1
    for (int gg = 0; gg < 4; gg++) {
        float a[8];
#pragma unroll
        for (int e = 0; e < 8; e++) {
            const float4* w4 = (const float4*)(swo + (gg * 8 + e) * 32);
            float b0 = 0, b1 = 0, b2 = 0, b3 = 0;
#pragma unroll
            for (int c = 0; c < 8; c++) {
                float4 w = w4[c];
                b0 = fmaf(o[4 * c], w.x, b0);
                b1 = fmaf(o[4 * c + 1], w.y, b1);
                b2 = fmaf(o[4 * c + 2], w.z, b2);
                b3 = fmaf(o[4 * c + 3], w.w, b3);
            }
            a[e] = (b0 + b1) + (b2 + b3);
        }
#pragma unroll
        for (int e = 0; e < 8; e++) {
            sumsq = fmaf(a[e], a[e], sumsq);
            scr[gg * 8 + e] = a[e];
        }
    }
    float rs1 = rsqrtf(sumsq * 0.03125f + 1e-6f);

    // ---- xn = x + rmsnorm(ow)  (reload x from gmem) ----
    float xn[32];
#pragma unroll
    for (int c = 0; c < 8; c++) {
        float4 xv = *(const float4*)(gx + 4 * c);
        float4 nw = *(const float4*)(snorm + 32 + 4 * c);
        xn[4 * c] = fmaf(scr[4 * c] * rs1, nw.x, xv.x);
        xn[4 * c + 1] = fmaf(scr[4 * c + 1] * rs1, nw.y, xv.y);
        xn[4 * c + 2] = fmaf(scr[4 * c + 2] * rs1, nw.z, xv.z);
        xn[4 * c + 3] = fmaf(scr[4 * c + 3] * rs1, nw.w, xv.w);
    }

    // ---- h2 = rmsnorm(xn) ----
    float h2[32];
    {
        float s0 = 0, s1 = 0, s2 = 0, s3 = 0;
#pragma unroll
        for (int c = 0; c < 8; c++) {
            s0 = fmaf(xn[4 * c], xn[4 * c], s0);
            s1 = fmaf(xn[4 * c + 1], xn[4 * c + 1], s1);
            s2 = fmaf(xn[4 * c + 2], xn[4 * c + 2], s2);
            s3 = fmaf(xn[4 * c + 3], xn[4 * c + 3], s3);
        }
        float rs2 = rsqrtf(((s0 + s1) + (s2 + s3)) * 0.03125f + 1e-6f);
#pragma unroll
        for (int c = 0; c < 8; c++) {
            float4 nw = *(const float4*)(snorm + 64 + 4 * c);
            h2[4 * c] = xn[4 * c] * rs2 * nw.x;
            h2[4 * c + 1] = xn[4 * c + 1] * rs2 * nw.y;
            h2[4 * c + 2] = xn[4 * c + 2] * rs2 * nw.z;
            h2[4 * c + 3] = xn[4 * c + 3] * rs2 * nw.w;
        }
    }

    // ---- FFN: f-groups of 4, accumulate straight into outv ----
    float ov[32];
#pragma unroll
    for (int d = 0; d < 32; d++) ov[d] = 0.f;

#pragma unroll 1
    for (int fg = 0; fg < 16; fg++) {
        float f4v[4];
#pragma unroll
        for (int e = 0; e < 4; e++) {
            const float4* wg4 = (const float4*)(swg + (fg * 4 + e) * 32);
            const float4* wu4 = (const float4*)(swu + (fg * 4 + e) * 32);
            float g0 = 0, g1 = 0, u0 = 0, u1 = 0;
#pragma unroll
            for (int c = 0; c < 8; c++) {
                float4 wg = wg4[c];
                float4 wu = wu4[c];
                g0 = fmaf(h2[4 * c], wg.x, g0);
                g1 = fmaf(h2[4 * c + 1], wg.y, g1);
                g0 = fmaf(h2[4 * c + 2], wg.z, g0);
                g1 = fmaf(h2[4 * c + 3], wg.w, g1);
                u0 = fmaf(h2[4 * c], wu.x, u0);
                u1 = fmaf(h2[4 * c + 1], wu.y, u1);
                u0 = fmaf(h2[4 * c + 2], wu.z, u0);
                u1 = fmaf(h2[4 * c + 3], wu.w, u1);
            }
            float g = g0 + g1;
            float u = u0 + u1;
            f4v[e] = __fdividef(g, 1.f + __expf(-g)) * u;
        }
#pragma unroll
        for (int d = 0; d < 32; d++) {
            float4 w = *(const float4*)(swout + d * 64 + fg * 4);
            ov[d] = fmaf(f4v[0], w.x,
                    fmaf(f4v[1], w.y,
                    fmaf(f4v[2], w.z, fmaf(f4v[3], w.w, ov[d]))));
        }
    }

    // ---- out = xn + rmsnorm(ov) ----
    {
        float s0 = 0, s1 = 0, s2 = 0, s3 = 0;
#pragma unroll
        for (int c = 0; c < 8; c++) {
            s0 = fmaf(ov[4 * c], ov[4 * c], s0);
            s1 = fmaf(ov[4 * c + 1], ov[4 * c + 1], s1);
            s2 = fmaf(ov[4 * c + 2], ov[4 * c + 2], s2);
            s3 = fmaf(ov[4 * c + 3], ov[4 * c + 3], s3);
        }
        float rs3 = rsqrtf(((s0 + s1) + (s2 + s3)) * 0.03125f + 1e-6f);
        if (valid) {
#pragma unroll
            for (int c = 0; c < 8; c++) {
                float4 nw = *(const float4*)(snorm + 96 + 4 * c);
                float4 r;
                r.x = fmaf(ov[4 * c] * rs3, nw.x, xn[4 * c]);
                r.y = fmaf(ov[4 * c + 1] * rs3, nw.y, xn[4 * c + 1]);
                r.z = fmaf(ov[4 * c + 2] * rs3, nw.z, xn[4 * c + 2]);
                r.w = fmaf(ov[4 * c + 3] * rs3, nw.w, xn[4 * c + 3]);
                *(float4*)(gx + 4 * c) = r;
            }
        }
    }
}

// ---------------------------------------------------------------------------
// Final: rmsnorm + extract 3 CLS tokens of last timestep.
// ---------------------------------------------------------------------------
__global__ void final_kernel(const float* __restrict__ fnorm, float* __restrict__ out) {
    int b = blockIdx.x / 3, k = blockIdx.x % 3, lane = threadIdx.x;
    float x = g_tokens[(((long)b * 128 + 127) * 67 + 64 + k) * 32 + lane];
    float ms = warp_sum(x * x) * (1.f / 32.f);
    out[(k * 16 + b) * 32 + lane] = x * rsqrtf(ms + 1e-6f) * fnorm[lane];
}

// ---------------------------------------------------------------------------
// Launch
// ---------------------------------------------------------------------------
extern "C" void kernel_launch(void* const* d_in, const int* in_sizes, int n_in,
                              void* d_out, int out_size) {
    const float* obs    = (const float*)d_in[0];
    const float* Wval   = (const float*)d_in[1];
    const float* bval   = (const float*)d_in[2];
    const float* innorm = (const float*)d_in[3];
    const float* dimemb = (const float*)d_in[4];
    const float* cls    = (const float*)d_in[5];
    const float* fnorm  = (const float*)d_in[6];
    const float* sWq   = (const float*)d_in[7];
    const float* sWk   = (const float*)d_in[8];
    const float* sWv   = (const float*)d_in[9];
    const float* sWo   = (const float*)d_in[10];
    const float* sWg   = (const float*)d_in[11];
    const float* sWu   = (const float*)d_in[12];
    const float* sWout = (const float*)d_in[13];
    const float* sN4   = (const float*)d_in[14];
    const float* sQKN  = (const float*)d_in[15];
    const float* tWq   = (const float*)d_in[16];
    const float* tWk   = (const float*)d_in[17];
    const float* tWv   = (const float*)d_in[18];
    const float* tWo   = (const float*)d_in[19];
    const float* tWg   = (const float*)d_in[20];
    const float* tWu   = (const float*)d_in[21];
    const float* tWout = (const float*)d_in[22];
    const float* tN4   = (const float*)d_in[23];
    const float* tQKN  = (const float*)d_in[24];

    // smem bytes: (KVSZ + 10240 + 144) * 4
    const int SZ_S = (3 * 2 * 67 * 36 + 10240 + 144) * 4;   // 99424
    const int SZ_T = (2 * 2 * 128 * 36 + 10240 + 144) * 4;  // 115264

    cudaFuncSetAttribute(attn_tpl<67, 3, false>, cudaFuncAttributeMaxDynamicSharedMemorySize, SZ_S);
    cudaFuncSetAttribute(attn_tpl<128, 2, true>, cudaFuncAttributeMaxDynamicSharedMemorySize, SZ_T);

    embed_kernel<<<2048, 256>>>(obs, Wval, bval, innorm, dimemb, cls);

    const int GRID_S = (2048 + 2) / 3;   // 683
    const int GRID_T = 1072 / 2;         // 536

    for (int layer = 0; layer < 3; layer++) {
        attn_tpl<67, 3, false><<<GRID_S, 224, SZ_S>>>(
            sWq + layer * 1024, sWk + layer * 1024, sWv + layer * 1024, sWo + layer * 1024,
            sWg + layer * 2048, sWu + layer * 2048, sWout + layer * 2048,
            sN4 + layer * 128, sQKN + layer * 16, 2048);
        if (layer < 2) {
            attn_tpl<128, 2, true><<<GRID_T, 256, SZ_T>>>(
                tWq + layer * 1024, tWk + layer * 1024, tWv + layer * 1024, tWo + layer * 1024,
                tWg + layer * 2048, tWu + layer * 2048, tWout + layer * 2048,
                tN4 + layer * 128, tQKN + layer * 16, 1072);
        }
    }

    final_kernel<<<48, 32>>>(fnorm, (float*)d_out);
}

// round 4
// speedup vs baseline: 2.7179x; 1.0797x over previous
#include <cuda_runtime.h>
#include <math.h>

#define FULL 0xffffffffu
typedef unsigned long long u64;

// Scratch token buffer: (B=16, T=128, slots=67, EMBED=32) fp32
__device__ float g_tokens[16 * 128 * 67 * 32];

__device__ __forceinline__ float warp_sum(float v) {
    v += __shfl_xor_sync(FULL, v, 16);
    v += __shfl_xor_sync(FULL, v, 8);
    v += __shfl_xor_sync(FULL, v, 4);
    v += __shfl_xor_sync(FULL, v, 2);
    v += __shfl_xor_sync(FULL, v, 1);
    return v;
}

// ---- packed f32x2 helpers (Blackwell FFMA2 path) ----
__device__ __forceinline__ u64 fma2(u64 a, u64 b, u64 c) {
    u64 d; asm("fma.rn.f32x2 %0, %1, %2, %3;" : "=l"(d) : "l"(a), "l"(b), "l"(c)); return d;
}
__device__ __forceinline__ u64 mul2(u64 a, u64 b) {
    u64 d; asm("mul.rn.f32x2 %0, %1, %2;" : "=l"(d) : "l"(a), "l"(b)); return d;
}
__device__ __forceinline__ u64 add2(u64 a, u64 b) {
    u64 d; asm("add.rn.f32x2 %0, %1, %2;" : "=l"(d) : "l"(a), "l"(b)); return d;
}
__device__ __forceinline__ u64 pack2(float lo, float hi) {
    u64 d; asm("mov.b64 %0, {%1, %2};" : "=l"(d) : "f"(lo), "f"(hi)); return d;
}
__device__ __forceinline__ float hsum2(u64 v) {
    float lo, hi; asm("mov.b64 {%0, %1}, %2;" : "=f"(lo), "=f"(hi) : "l"(v)); return lo + hi;
}

// load 32 floats (16B-aligned) as 16 packed u64
__device__ __forceinline__ void ld_row16(u64* r, const float* p) {
    const ulonglong2* q = (const ulonglong2*)p;
#pragma unroll
    for (int i = 0; i < 8; i++) { ulonglong2 t = q[i]; r[2 * i] = t.x; r[2 * i + 1] = t.y; }
}

// dot of 32-float smem row with packed vector v2[16]
__device__ __forceinline__ float dot32(const float* wrow, const u64* v2) {
    const ulonglong2* w = (const ulonglong2*)wrow;
    ulonglong2 t0 = w[0], t1 = w[1];
    u64 a0 = mul2(v2[0], t0.x); a0 = fma2(v2[1], t0.y, a0);
    u64 a1 = mul2(v2[2], t1.x); a1 = fma2(v2[3], t1.y, a1);
#pragma unroll
    for (int i = 2; i < 8; i += 2) {
        ulonglong2 u0 = w[i], u1 = w[i + 1];
        a0 = fma2(v2[2 * i], u0.x, a0);
        a0 = fma2(v2[2 * i + 1], u0.y, a0);
        a1 = fma2(v2[2 * i + 2], u1.x, a1);
        a1 = fma2(v2[2 * i + 3], u1.y, a1);
    }
    return hsum2(add2(a0, a1));
}

__device__ __forceinline__ float sumsq16(const u64* v) {
    u64 a0 = mul2(v[0], v[0]);
    u64 a1 = mul2(v[1], v[1]);
#pragma unroll
    for (int i = 2; i < 16; i += 2) {
        a0 = fma2(v[i], v[i], a0);
        a1 = fma2(v[i + 1], v[i + 1], a1);
    }
    return hsum2(add2(a0, a1));
}

// ---------------------------------------------------------------------------
// Kernel 0: tokenize + input rmsnorm. grid = B*T (2048), block = 256.
// ---------------------------------------------------------------------------
__global__ void embed_kernel(const float* __restrict__ obs,
                             const float* __restrict__ Wval,
                             const float* __restrict__ bval,
                             const float* __restrict__ innorm,
                             const float* __restrict__ dimemb,
                             const float* __restrict__ cls) {
    int bt = blockIdx.x;
    int tid = threadIdx.x;
    int wid = tid >> 5, lane = tid & 31;
    for (int s = wid; s < 67; s += 8) {
        float val;
        if (s < 64)
            val = fmaf(obs[bt * 64 + s], Wval[lane], bval[lane]) + dimemb[s * 32 + lane];
        else
            val = cls[(s - 64) * 32 + lane];
        float ms = warp_sum(val * val) * (1.f / 32.f);
        g_tokens[(bt * 67 + s) * 32 + lane] = val * rsqrtf(ms + 1e-6f) * innorm[lane];
    }
}

// ---------------------------------------------------------------------------
// Token-per-lane fused attention block, f32x2 packed math.
// ---------------------------------------------------------------------------
template <int S, int NSEQ, bool TEMPORAL>
__global__ void __launch_bounds__(32 * ((S * NSEQ + 31) / 32), 2)
attn_tpl(const float* __restrict__ Wq, const float* __restrict__ Wk,
         const float* __restrict__ Wv, const float* __restrict__ Wo,
         const float* __restrict__ Wg, const float* __restrict__ Wu,
         const float* __restrict__ Wout, const float* __restrict__ norm4,
         const float* __restrict__ qkn, int nseq_total) {
    constexpr int BLK = 32 * ((S * NSEQ + 31) / 32);
    constexpr int KVROW = 36;
    constexpr int KVSZ = NSEQ * 2 * S * KVROW;

    extern __shared__ float sm[];
    float* skv   = sm;                // KVSZ
    float* swq   = skv + KVSZ;        // 1024
    float* swk   = swq + 1024;
    float* swv   = swk + 1024;
    float* swo   = swv + 1024;
    float* swg   = swo + 1024;        // 2048
    float* swu   = swg + 2048;        // 2048
    float* swout = swu + 2048;        // 2048 (stored TRANSPOSED: [f][d])
    float* snorm = swout + 2048;      // 128
    float* sqkn  = snorm + 128;       // 16

    const int tid = threadIdx.x;

    // ---- stage weights ----
    for (int i = tid; i < 256; i += BLK) {
        ((float4*)swq)[i] = ((const float4*)Wq)[i];
        ((float4*)swk)[i] = ((const float4*)Wk)[i];
        ((float4*)swv)[i] = ((const float4*)Wv)[i];
        ((float4*)swo)[i] = ((const float4*)Wo)[i];
    }
    for (int i = tid; i < 512; i += BLK) {
        ((float4*)swg)[i] = ((const float4*)Wg)[i];
        ((float4*)swu)[i] = ((const float4*)Wu)[i];
    }
    for (int i = tid; i < 2048; i += BLK) {     // transpose Wout -> [f][d]
        int f = i >> 5, d = i & 31;
        swout[i] = Wout[d * 64 + f];
    }
    if (tid < 32) ((float4*)snorm)[tid] = ((const float4*)norm4)[tid];
    if (tid < 4) ((float4*)sqkn)[tid] = ((const float4*)qkn)[tid];
    __syncthreads();

    // ---- per-lane token assignment ----
    int gseq0 = blockIdx.x * NSEQ;
    int nvalid = (min(gseq0 + NSEQ, nseq_total) - gseq0) * S;
    bool valid = tid < nvalid;
    int tcl = valid ? tid : (nvalid - 1);
    int seq = tcl / S;
    int tok = tcl - seq * S;

    float* kb = skv + seq * (2 * S * KVROW);
    float* vb = kb + S * KVROW;

    float* gx;
    if (TEMPORAL) {
        int gs = gseq0 + seq;
        int b = gs / 67, sl = gs - b * 67;
        gx = g_tokens + ((long)b * 128 * 67 + (long)tok * 67 + sl) * 32;
    } else {
        gx = g_tokens + ((long)(gseq0 + seq) * 67 + tok) * 32;
    }

    float qknQ[8], qknK[8];
#pragma unroll
    for (int e = 0; e < 8; e++) {
        qknQ[e] = sqkn[e] * 0.35355339059327373f;   // fold 1/sqrt(HD)
        qknK[e] = sqkn[8 + e];
    }

    float cs4[4], sn4[4];
    if (TEMPORAL) {
        const float th[4] = {1.f, 0.1f, 0.01f, 0.001f};
#pragma unroll
        for (int j = 0; j < 4; j++) __sincosf((float)tok * th[j], &sn4[j], &cs4[j]);
    }

    // ================= Phase B: h = rmsnorm(x); K,V,Q projections ==========
    u64 h2[16];
    {
        u64 x2[16];
        ld_row16(x2, gx);
        float rs = rsqrtf(sumsq16(x2) * 0.03125f + 1e-6f);
        u64 rs2 = pack2(rs, rs);
        const ulonglong2* nw = (const ulonglong2*)snorm;
#pragma unroll
        for (int i = 0; i < 8; i++) {
            ulonglong2 n = nw[i];
            h2[2 * i] = mul2(mul2(x2[2 * i], rs2), n.x);
            h2[2 * i + 1] = mul2(mul2(x2[2 * i + 1], rs2), n.y);
        }
    }

    // ---- K heads ----
#pragma unroll 1
    for (int hh = 0; hh < 4; hh++) {
        float a[8];
#pragma unroll
        for (int e = 0; e < 8; e++) a[e] = dot32(swk + (hh * 8 + e) * 32, h2);
        float ms = 0;
#pragma unroll
        for (int e = 0; e < 8; e++) ms = fmaf(a[e], a[e], ms);
        float sc = rsqrtf(ms * 0.125f + 1e-6f);
#pragma unroll
        for (int e = 0; e < 8; e++) a[e] *= sc * qknK[e];
        if (TEMPORAL) {
#pragma unroll
            for (int e = 0; e < 4; e++) {
                float aa = a[e], bb = a[e + 4];
                a[e] = aa * cs4[e] - bb * sn4[e];
                a[e + 4] = fmaf(aa, sn4[e], bb * cs4[e]);
            }
        }
        if (valid) {
            float* dst = kb + tok * KVROW + hh * 8;
            *(float4*)dst = make_float4(a[0], a[1], a[2], a[3]);
            *(float4*)(dst + 4) = make_float4(a[4], a[5], a[6], a[7]);
        }
    }

    // ---- V heads ----
#pragma unroll 1
    for (int hh = 0; hh < 4; hh++) {
        float a[8];
#pragma unroll
        for (int e = 0; e < 8; e++) a[e] = dot32(swv + (hh * 8 + e) * 32, h2);
        if (valid) {
            float* dst = vb + tok * KVROW + hh * 8;
            *(float4*)dst = make_float4(a[0], a[1], a[2], a[3]);
            *(float4*)(dst + 4) = make_float4(a[4], a[5], a[6], a[7]);
        }
    }

    // ---- Q heads (packed for attention) ----
    u64 q2[16];
#pragma unroll
    for (int hh = 0; hh < 4; hh++) {
        float a[8];
#pragma unroll
        for (int e = 0; e < 8; e++) a[e] = dot32(swq + (hh * 8 + e) * 32, h2);
        float ms = 0;
#pragma unroll
        for (int e = 0; e < 8; e++) ms = fmaf(a[e], a[e], ms);
        float sc = rsqrtf(ms * 0.125f + 1e-6f);
#pragma unroll
        for (int e = 0; e < 8; e++) a[e] *= sc * qknQ[e];
        if (TEMPORAL) {
#pragma unroll
            for (int e = 0; e < 4; e++) {
                float aa = a[e], bb = a[e + 4];
                a[e] = aa * cs4[e] - bb * sn4[e];
                a[e + 4] = fmaf(aa, sn4[e], bb * cs4[e]);
            }
        }
#pragma unroll
        for (int j = 0; j < 4; j++) q2[4 * hh + j] = pack2(a[2 * j], a[2 * j + 1]);
    }
    __syncthreads();

    // ================= Phase C: streaming attention ========================
    u64 o2[16];
#pragma unroll
    for (int i = 0; i < 16; i++) o2[i] = 0ULL;
    float l[4] = {0.f, 0.f, 0.f, 0.f};

#pragma unroll 1
    for (int j = 0; j < S; j++) {
        u64 k2[16];
        ld_row16(k2, kb + j * KVROW);
        float p[4];
#pragma unroll
        for (int hh = 0; hh < 4; hh++) {
            u64 c0 = fma2(q2[4 * hh + 1], k2[4 * hh + 1], mul2(q2[4 * hh], k2[4 * hh]));
            u64 c1 = fma2(q2[4 * hh + 3], k2[4 * hh + 3], mul2(q2[4 * hh + 2], k2[4 * hh + 2]));
            float s = hsum2(add2(c0, c1));
            p[hh] = __expf(s);
            l[hh] += p[hh];
        }
        u64 v2[16];
        ld_row16(v2, vb + j * KVROW);
#pragma unroll
        for (int hh = 0; hh < 4; hh++) {
            u64 pp = pack2(p[hh], p[hh]);
#pragma unroll
            for (int i = 0; i < 4; i++)
                o2[4 * hh + i] = fma2(pp, v2[4 * hh + i], o2[4 * hh + i]);
        }
    }
#pragma unroll
    for (int hh = 0; hh < 4; hh++) {
        float li = __fdividef(1.f, l[hh]);
        u64 li2 = pack2(li, li);
#pragma unroll
        for (int i = 0; i < 4; i++) o2[4 * hh + i] = mul2(o2[4 * hh + i], li2);
    }

    // ---- Wo + rmsnorm residual (all in registers) ----
    float ow[32];
    float sumsq = 0.f;
#pragma unroll
    for (int d = 0; d < 32; d++) {
        ow[d] = dot32(swo + d * 32, o2);
        sumsq = fmaf(ow[d], ow[d], sumsq);
    }
    float rs1 = rsqrtf(sumsq * 0.03125f + 1e-6f);
    u64 rs12 = pack2(rs1, rs1);

    u64 xn2[16];
    {
        u64 x2[16];
        ld_row16(x2, gx);
        const ulonglong2* nw = (const ulonglong2*)(snorm + 32);
#pragma unroll
        for (int i = 0; i < 8; i++) {
            ulonglong2 n = nw[i];
            u64 w0 = pack2(ow[4 * i], ow[4 * i + 1]);
            u64 w1 = pack2(ow[4 * i + 2], ow[4 * i + 3]);
            xn2[2 * i] = fma2(mul2(w0, rs12), n.x, x2[2 * i]);
            xn2[2 * i + 1] = fma2(mul2(w1, rs12), n.y, x2[2 * i + 1]);
        }
    }

    // ---- h2v = rmsnorm(xn) ----
    u64 h2v[16];
    {
        float rs = rsqrtf(sumsq16(xn2) * 0.03125f + 1e-6f);
        u64 rs2 = pack2(rs, rs);
        const ulonglong2* nw = (const ulonglong2*)(snorm + 64);
#pragma unroll
        for (int i = 0; i < 8; i++) {
            ulonglong2 n = nw[i];
            h2v[2 * i] = mul2(mul2(xn2[2 * i], rs2), n.x);
            h2v[2 * i + 1] = mul2(mul2(xn2[2 * i + 1], rs2), n.y);
        }
    }

    // ---- FFN (gate/up dots, Wout accumulation with transposed rows) ----
    u64 ov2[16];
#pragma unroll
    for (int i = 0; i < 16; i++) ov2[i] = 0ULL;

#pragma unroll 1
    for (int fg = 0; fg < 16; fg++) {
#pragma unroll
        for (int e = 0; e < 4; e++) {
            int f = fg * 4 + e;
            float g = dot32(swg + f * 32, h2v);
            float u = dot32(swu + f * 32, h2v);
            float fv = __fdividef(g, 1.f + __expf(-g)) * u;
            u64 f2 = pack2(fv, fv);
            const ulonglong2* wr = (const ulonglong2*)(swout + f * 32);
#pragma unroll
            for (int i = 0; i < 8; i++) {
                ulonglong2 t = wr[i];
                ov2[2 * i] = fma2(f2, t.x, ov2[2 * i]);
                ov2[2 * i + 1] = fma2(f2, t.y, ov2[2 * i + 1]);
            }
        }
    }

    // ---- out = xn + rmsnorm(ov) ----
    {
        float rs3 = rsqrtf(sumsq16(ov2) * 0.03125f + 1e-6f);
        u64 rs32 = pack2(rs3, rs3);
        const ulonglong2* nw = (const ulonglong2*)(snorm + 96);
        if (valid) {
            ulonglong2* gxo = (ulonglong2*)gx;
#pragma unroll
            for (int i = 0; i < 8; i++) {
                ulonglong2 n = nw[i];
                ulonglong2 r;
                r.x = fma2(mul2(ov2[2 * i], rs32), n.x, xn2[2 * i]);
                r.y = fma2(mul2(ov2[2 * i + 1], rs32), n.y, xn2[2 * i + 1]);
                gxo[i] = r;
            }
        }
    }
}

// ---------------------------------------------------------------------------
// Final: rmsnorm + extract 3 CLS tokens of last timestep.
// ---------------------------------------------------------------------------
__global__ void final_kernel(const float* __restrict__ fnorm, float* __restrict__ out) {
    int b = blockIdx.x / 3, k = blockIdx.x % 3, lane = threadIdx.x;
    float x = g_tokens[(((long)b * 128 + 127) * 67 + 64 + k) * 32 + lane];
    float ms = warp_sum(x * x) * (1.f / 32.f);
    out[(k * 16 + b) * 32 + lane] = x * rsqrtf(ms + 1e-6f) * fnorm[lane];
}

// ---------------------------------------------------------------------------
// Launch
// ---------------------------------------------------------------------------
extern "C" void kernel_launch(void* const* d_in, const int* in_sizes, int n_in,
                              void* d_out, int out_size) {
    const float* obs    = (const float*)d_in[0];
    const float* Wval   = (const float*)d_in[1];
    const float* bval   = (const float*)d_in[2];
    const float* innorm = (const float*)d_in[3];
    const float* dimemb = (const float*)d_in[4];
    const float* cls    = (const float*)d_in[5];
    const float* fnorm  = (const float*)d_in[6];
    const float* sWq   = (const float*)d_in[7];
    const float* sWk   = (const float*)d_in[8];
    const float* sWv   = (const float*)d_in[9];
    const float* sWo   = (const float*)d_in[10];
    const float* sWg   = (const float*)d_in[11];
    const float* sWu   = (const float*)d_in[12];
    const float* sWout = (const float*)d_in[13];
    const float* sN4   = (const float*)d_in[14];
    const float* sQKN  = (const float*)d_in[15];
    const float* tWq   = (const float*)d_in[16];
    const float* tWk   = (const float*)d_in[17];
    const float* tWv   = (const float*)d_in[18];
    const float* tWo   = (const float*)d_in[19];
    const float* tWg   = (const float*)d_in[20];
    const float* tWu   = (const float*)d_in[21];
    const float* tWout = (const float*)d_in[22];
    const float* tN4   = (const float*)d_in[23];
    const float* tQKN  = (const float*)d_in[24];

    const int SZ_S = (3 * 2 * 67 * 36 + 10240 + 144) * 4;   // 99424
    const int SZ_T = (2 * 2 * 128 * 36 + 10240 + 144) * 4;  // 115264

    cudaFuncSetAttribute(attn_tpl<67, 3, false>, cudaFuncAttributeMaxDynamicSharedMemorySize, SZ_S);
    cudaFuncSetAttribute(attn_tpl<128, 2, true>, cudaFuncAttributeMaxDynamicSharedMemorySize, SZ_T);

    embed_kernel<<<2048, 256>>>(obs, Wval, bval, innorm, dimemb, cls);

    const int GRID_S = (2048 + 2) / 3;   // 683
    const int GRID_T = 1072 / 2;         // 536

    for (int layer = 0; layer < 3; layer++) {
        attn_tpl<67, 3, false><<<GRID_S, 224, SZ_S>>>(
            sWq + layer * 1024, sWk + layer * 1024, sWv + layer * 1024, sWo + layer * 1024,
            sWg + layer * 2048, sWu + layer * 2048, sWout + layer * 2048,
            sN4 + layer * 128, sQKN + layer * 16, 2048);
        if (layer < 2) {
            attn_tpl<128, 2, true><<<GRID_T, 256, SZ_T>>>(
                tWq + layer * 1024, tWk + layer * 1024, tWv + layer * 1024, tWo + layer * 1024,
                tWg + layer * 2048, tWu + layer * 2048, tWout + layer * 2048,
                tN4 + layer * 128, tQKN + layer * 16, 1072);
        }
    }

    final_kernel<<<48, 32>>>(fnorm, (float*)d_out);
}